// round 2
// baseline (speedup 1.0000x reference)
#include <cuda_runtime.h>
#include <cuda_bf16.h>

// Gridding: trilinear splat of B=32 x N=262144 points into per-batch 64^3 grid.
// out[b, (x*64+y)*64+z] += trilinear weights, masked where sum(pt*scale)==0.

#define GRID_S   32          // half-extent (scale)
#define GRID_G   64          // side length
#define GRID_V   (GRID_G*GRID_G*GRID_G)   // 262144
#define NPTS_LOG2 18         // N = 262144 per batch

__global__ __launch_bounds__(256)
void gridding_scatter_kernel(const float* __restrict__ pt,
                             float* __restrict__ out,
                             int total_pts)
{
    int i = blockIdx.x * blockDim.x + threadIdx.x;
    if (i >= total_pts) return;

    // coalesced: warp reads a contiguous 384B region
    float x = pt[3 * i + 0] * (float)GRID_S;
    float y = pt[3 * i + 1] * (float)GRID_S;
    float z = pt[3 * i + 2] * (float)GRID_S;

    // mask: drop points whose scaled coord-sum is exactly 0
    // (scaling by 32 = 2^5 is exact, so this matches sum(unscaled)*32 == 0)
    float m = ((x + y + z) != 0.0f) ? 1.0f : 0.0f;

    float fx = floorf(x), fy = floorf(y), fz = floorf(z);
    float dx = x - fx, dy = y - fy, dz = z - fz;   // fractions from UNCLIPPED floor

    int ix = min(max(__float2int_rn(fx) + GRID_S, 0), GRID_G - 2);
    int iy = min(max(__float2int_rn(fy) + GRID_S, 0), GRID_G - 2);
    int iz = min(max(__float2int_rn(fz) + GRID_S, 0), GRID_G - 2);

    // fold mask into x-axis weights
    float wx0 = (1.0f - dx) * m;
    float wx1 = dx * m;
    float wy0 = 1.0f - dy, wy1 = dy;
    float wz0 = 1.0f - dz, wz1 = dz;

    int b = i >> NPTS_LOG2;                 // batch index (N = 2^18)
    float* g = out + ((long long)b << NPTS_LOG2);  // G^3 == N == 2^18 floats per batch

    int f = (ix * GRID_G + iy) * GRID_G + iz;

    float w00 = wx0 * wy0;
    float w01 = wx0 * wy1;
    float w10 = wx1 * wy0;
    float w11 = wx1 * wy1;

    // neighbor offsets: z:+1, y:+64, x:+4096
    atomicAdd(&g[f],                 w00 * wz0);
    atomicAdd(&g[f + 1],             w00 * wz1);
    atomicAdd(&g[f + GRID_G],        w01 * wz0);
    atomicAdd(&g[f + GRID_G + 1],    w01 * wz1);
    atomicAdd(&g[f + GRID_G*GRID_G],          w10 * wz0);
    atomicAdd(&g[f + GRID_G*GRID_G + 1],      w10 * wz1);
    atomicAdd(&g[f + GRID_G*GRID_G + GRID_G], w11 * wz0);
    atomicAdd(&g[f + GRID_G*GRID_G + GRID_G + 1], w11 * wz1);
}

extern "C" void kernel_launch(void* const* d_in, const int* in_sizes, int n_in,
                              void* d_out, int out_size)
{
    const float* ptcloud = (const float*)d_in[0];
    float* out = (float*)d_out;

    int total_pts = in_sizes[0] / 3;   // 32 * 262144 = 8388608

    // harness poisons d_out; zero it (capturable memset node)
    cudaMemsetAsync(d_out, 0, (size_t)out_size * sizeof(float), 0);

    int threads = 256;
    int blocks = (total_pts + threads - 1) / threads;
    gridding_scatter_kernel<<<blocks, threads>>>(ptcloud, out, total_pts);
}

// round 4
// speedup vs baseline: 1.5408x; 1.5408x over previous
#include <cuda_runtime.h>
#include <cuda_bf16.h>

// Gridding: trilinear splat of B=32 x N=262144 points into per-batch 64^3 grid.
// R2: vector reductions (red.global.add.v4/.v2.f32) to merge the z-adjacent
// corner pairs into single L2 RMW transactions. 8 -> avg 5 transactions/point.

#define GRID_S   32
#define GRID_G   64
#define NPTS_LOG2 18

__device__ __forceinline__ void red_v4(float* p, float a, float b, float c, float d) {
    asm volatile("red.global.add.v4.f32 [%0], {%1, %2, %3, %4};"
                 :: "l"(p), "f"(a), "f"(b), "f"(c), "f"(d) : "memory");
}
__device__ __forceinline__ void red_v2(float* p, float a, float b) {
    asm volatile("red.global.add.v2.f32 [%0], {%1, %2};"
                 :: "l"(p), "f"(a), "f"(b) : "memory");
}

__global__ __launch_bounds__(256)
void gridding_scatter_kernel(const float* __restrict__ pt,
                             float* __restrict__ out,
                             int total_pts)
{
    int i = blockIdx.x * blockDim.x + threadIdx.x;
    if (i >= total_pts) return;

    float x = pt[3 * i + 0] * (float)GRID_S;
    float y = pt[3 * i + 1] * (float)GRID_S;
    float z = pt[3 * i + 2] * (float)GRID_S;

    // mask: drop points whose scaled coord-sum is exactly 0 (x32 scaling is exact)
    float m = ((x + y + z) != 0.0f) ? 1.0f : 0.0f;

    float fx = floorf(x), fy = floorf(y), fz = floorf(z);
    float dx = x - fx, dy = y - fy, dz = z - fz;   // fractions from UNCLIPPED floor

    int ix = min(max(__float2int_rn(fx) + GRID_S, 0), GRID_G - 2);
    int iy = min(max(__float2int_rn(fy) + GRID_S, 0), GRID_G - 2);
    int iz = min(max(__float2int_rn(fz) + GRID_S, 0), GRID_G - 2);

    float wx0 = (1.0f - dx) * m;
    float wx1 = dx * m;
    float wy0 = 1.0f - dy, wy1 = dy;
    float wz0 = 1.0f - dz, wz1 = dz;

    int b = i >> NPTS_LOG2;
    float* g = out + ((long long)b << NPTS_LOG2);   // G^3 == 2^18 floats/batch

    int f = (ix * GRID_G + iy) * GRID_G + iz;

    float w00 = wx0 * wy0;   // corner (x0,y0): offset 0
    float w01 = wx0 * wy1;   // (x0,y1): +64
    float w10 = wx1 * wy0;   // (x1,y0): +4096
    float w11 = wx1 * wy1;   // (x1,y1): +4160

    int r = iz & 3;          // f % 4 == iz % 4 (upper part of f is mult of 64)
    if (r < 3) {
        // z-pair fits in one 16B-aligned v4: lanes r and r+1
        float l0 = (r == 0) ? wz0 : 0.0f;
        float l1 = (r == 0) ? wz1 : ((r == 1) ? wz0 : 0.0f);
        float l2 = (r == 1) ? wz1 : ((r == 2) ? wz0 : 0.0f);
        float l3 = (r == 2) ? wz1 : 0.0f;
        float* base = g + (f - r);               // 16B aligned
        red_v4(base,                         w00 * l0, w00 * l1, w00 * l2, w00 * l3);
        red_v4(base + GRID_G,                w01 * l0, w01 * l1, w01 * l2, w01 * l3);
        red_v4(base + GRID_G * GRID_G,           w10 * l0, w10 * l1, w10 * l2, w10 * l3);
        red_v4(base + GRID_G * GRID_G + GRID_G,  w11 * l0, w11 * l1, w11 * l2, w11 * l3);
    } else {
        // iz % 4 == 3: pair straddles 16B boundary -> two 8B-aligned v2 per corner
        float* lo = g + (f - 1);                 // 8B aligned (f odd)
        float* hi = g + (f + 1);                 // 8B aligned
        red_v2(lo,                          0.0f, w00 * wz0);
        red_v2(hi,                          w00 * wz1, 0.0f);
        red_v2(lo + GRID_G,                 0.0f, w01 * wz0);
        red_v2(hi + GRID_G,                 w01 * wz1, 0.0f);
        red_v2(lo + GRID_G * GRID_G,            0.0f, w10 * wz0);
        red_v2(hi + GRID_G * GRID_G,            w10 * wz1, 0.0f);
        red_v2(lo + GRID_G * GRID_G + GRID_G,   0.0f, w11 * wz0);
        red_v2(hi + GRID_G * GRID_G + GRID_G,   w11 * wz1, 0.0f);
    }
}

extern "C" void kernel_launch(void* const* d_in, const int* in_sizes, int n_in,
                              void* d_out, int out_size)
{
    const float* ptcloud = (const float*)d_in[0];
    float* out = (float*)d_out;

    int total_pts = in_sizes[0] / 3;   // 32 * 262144 = 8388608

    cudaMemsetAsync(d_out, 0, (size_t)out_size * sizeof(float), 0);

    int threads = 256;
    int blocks = (total_pts + threads - 1) / threads;
    gridding_scatter_kernel<<<blocks, threads>>>(ptcloud, out, total_pts);
}

// round 5
// speedup vs baseline: 1.8245x; 1.1841x over previous
#include <cuda_runtime.h>
#include <cuda_bf16.h>

// Gridding: trilinear splat of B=32 x N=262144 points into per-batch 64^3 grid.
// R4: parity-grid scratch layout -> exactly 2 v4 REDs per point (was avg 5).
//
// Scratch layout (per phase φ in {0,1}): L_φ(x,y,z) = (x*32 + ((y-φ)>>1))*128 + 2z + ((y-φ)&1)
// A point's 4 corners at fixed x (y in {iy,iy+1}, z in {iz,iz+1}) are contiguous
// in L_{iy&1}. Alignment fixed by writing iz-odd quads into a grid shifted by -2
// (slot u contributes to position u+2). 4 grids: [φ][iz&1].
// Remap kernel: out(x,y,z) = sum of G[φ][0][v_φ] + G[φ][1][v_φ-2] over valid φ.

#define GRID_S   32
#define GRID_G   64
#define NPTS_LOG2 18
#define NBATCH   32

// 4 grids x 32 batches x 2^18 floats = 128 MB scratch
__device__ float g_scratch[4][NBATCH][1 << NPTS_LOG2];

__device__ __forceinline__ void red_v4(float* p, float a, float b, float c, float d) {
    asm volatile("red.global.add.v4.f32 [%0], {%1, %2, %3, %4};"
                 :: "l"(p), "f"(a), "f"(b), "f"(c), "f"(d) : "memory");
}

__global__ __launch_bounds__(256)
void gridding_scatter_kernel(const float* __restrict__ pt, int total_pts)
{
    int i = blockIdx.x * blockDim.x + threadIdx.x;
    if (i >= total_pts) return;

    float x = pt[3 * i + 0] * (float)GRID_S;
    float y = pt[3 * i + 1] * (float)GRID_S;
    float z = pt[3 * i + 2] * (float)GRID_S;

    // drop points whose scaled coord-sum is exactly 0 (x32 scaling is exact)
    float m = ((x + y + z) != 0.0f) ? 1.0f : 0.0f;

    float fx = floorf(x), fy = floorf(y), fz = floorf(z);
    float dx = x - fx, dy = y - fy, dz = z - fz;   // fractions from UNCLIPPED floor

    int ix = min(max(__float2int_rn(fx) + GRID_S, 0), GRID_G - 2);
    int iy = min(max(__float2int_rn(fy) + GRID_S, 0), GRID_G - 2);
    int iz = min(max(__float2int_rn(fz) + GRID_S, 0), GRID_G - 2);

    float wx0 = (1.0f - dx) * m;
    float wx1 = dx * m;
    float wy0 = 1.0f - dy, wy1 = dy;
    float wz0 = 1.0f - dz, wz1 = dz;

    int b   = i >> NPTS_LOG2;
    int phi = iy & 1;
    int zb  = iz & 1;
    int p   = iy >> 1;                       // == (iy - phi) >> 1

    int gidx = phi * 2 + zb;
    // base position (16B aligned): (ix*32 + p)*128 + 2*iz - 2*(iz&1)
    int pos = (ix << 12) + (p << 7) + 2 * (iz & ~1);
    float* base = &g_scratch[gidx][b][pos];

    // lanes: {(y0,z0), (y1,z0), (y0,z1), (y1,z1)}
    float a0 = wy0 * wz0, a1 = wy1 * wz0, a2 = wy0 * wz1, a3 = wy1 * wz1;
    red_v4(base,        wx0 * a0, wx0 * a1, wx0 * a2, wx0 * a3);
    red_v4(base + 4096, wx1 * a0, wx1 * a1, wx1 * a2, wx1 * a3);   // x+1: +32*128
}

__global__ __launch_bounds__(256)
void gridding_remap_kernel(float* __restrict__ out, int total)
{
    int idx = blockIdx.x * blockDim.x + threadIdx.x;
    if (idx >= total) return;

    int b = idx >> NPTS_LOG2;
    int v = idx & ((1 << NPTS_LOG2) - 1);
    int z = v & 63;
    int y = (v >> 6) & 63;
    int x = v >> 12;

    float acc = 0.0f;

    // phase 0: pair (y & ~1, y|1), always valid
    {
        int v0 = (x << 12) + ((y >> 1) << 7) + 2 * z + (y & 1);
        acc += g_scratch[0][b][v0];
        if (v0 >= 2) acc += g_scratch[1][b][v0 - 2];
    }
    // phase 1: pair ((y-1)&~1 + 1, ...), valid for 1 <= y <= 62
    if (y >= 1 && y <= 62) {
        int ym = y - 1;
        int v1 = (x << 12) + ((ym >> 1) << 7) + 2 * z + (ym & 1);
        acc += g_scratch[2][b][v1];
        if (v1 >= 2) acc += g_scratch[3][b][v1 - 2];
    }

    out[idx] = acc;
}

extern "C" void kernel_launch(void* const* d_in, const int* in_sizes, int n_in,
                              void* d_out, int out_size)
{
    const float* ptcloud = (const float*)d_in[0];
    float* out = (float*)d_out;

    int total_pts = in_sizes[0] / 3;           // 32 * 262144
    int total_out = out_size;                  // 32 * 262144

    // zero scratch (memset node, graph-capturable)
    void* scratch_ptr = nullptr;
    cudaGetSymbolAddress(&scratch_ptr, g_scratch);
    cudaMemsetAsync(scratch_ptr, 0, sizeof(g_scratch), 0);

    int threads = 256;
    int blocks = (total_pts + threads - 1) / threads;
    gridding_scatter_kernel<<<blocks, threads>>>(ptcloud, total_pts);

    int rblocks = (total_out + threads - 1) / threads;
    gridding_remap_kernel<<<rblocks, threads>>>(out, total_out);
}